// round 2
// baseline (speedup 1.0000x reference)
#include <cuda_runtime.h>
#include <cuda_bf16.h>
#include <cstdint>

// ---------------------------------------------------------------------------
// Problem constants
// ---------------------------------------------------------------------------
#define BB   2
#define NPTS 100000
#define RES  256
#define CIN_ 64
#define COUT_ 128

// d_out layout: [out_pool | before_pool | x_after | c]
#define OFF_POOL   0
#define SZ_POOL    (2*128*128*128)            // 4,194,304
#define OFF_BP     (SZ_POOL)
#define SZ_BP      (2*128*256*256)            // 16,777,216
#define OFF_XAFTER (OFF_BP + SZ_BP)
#define OFF_C      (OFF_XAFTER + SZ_BP)

// ---------------------------------------------------------------------------
// Scratch (device globals; allocation-free)
// ---------------------------------------------------------------------------
__device__ float g_h1[2*128*256*256];     // conv1 output (NCHW)
__device__ float g_featT[2*256*256*128];  // x_after transposed (NHWC) for gather
__device__ float g_sums[2*256*256*128];   // scatter sums [b][seg][ch]
__device__ float g_cnt[2*256*256];        // scatter counts

// ---------------------------------------------------------------------------
// zero scratch
// ---------------------------------------------------------------------------
__global__ void zero_kernel(float* a, int n4) {
    int i = blockIdx.x * blockDim.x + threadIdx.x;
    if (i < n4) ((float4*)a)[i] = make_float4(0.f, 0.f, 0.f, 0.f);
}

// ---------------------------------------------------------------------------
// 3x3 conv, pad 1, 256x256, COUT=128. Block: 256 thr, 32x32 px tile, 8 ocs.
// Each thread: 4 px (column in y) x 8 oc.  FUSE: += 1x1 conv of x2, and also
// write an NHWC transposed copy for the sampler.
// ---------------------------------------------------------------------------
template<int CIN, bool FUSE>
__global__ __launch_bounds__(256)
void conv3x3_kernel(const float* __restrict__ in, const float* __restrict__ w,
                    const float* __restrict__ bias,
                    const float* __restrict__ x2, const float* __restrict__ w1x1,
                    const float* __restrict__ b1x1,
                    float* __restrict__ out_nchw, float* __restrict__ out_nhwc)
{
    __shared__ float s_w[8*CIN*9];
    __shared__ float s_in[34*34];
    __shared__ float s_w1[FUSE ? 8*64 : 1];

    const int tid = threadIdx.x;
    const int bz  = blockIdx.z;
    const int b   = bz >> 4;
    const int ocg = bz & 15;
    const int gx0 = blockIdx.x * 32;
    const int gy0 = blockIdx.y * 32;
    const int tx  = tid & 31;
    const int yg  = tid >> 5;

    {   // preload weights for this oc-group
        const float* wsrc = w + (size_t)ocg * 8 * CIN * 9;
        for (int i = tid; i < 8*CIN*9; i += 256) s_w[i] = wsrc[i];
        if (FUSE) {
            const float* w1src = w1x1 + ocg * 8 * 64;
            for (int i = tid; i < 8*64; i += 256) s_w1[i] = w1src[i];
        }
    }

    float acc[8][4];
#pragma unroll
    for (int o = 0; o < 8; o++)
#pragma unroll
        for (int r = 0; r < 4; r++) acc[o][r] = 0.f;

    const int ly = yg * 4;
    for (int k = 0; k < CIN; k++) {
        __syncthreads();
        const float* inp = in + (((size_t)b * CIN + k) << 16);
        for (int i = tid; i < 34*34; i += 256) {
            int rr = i / 34;
            int cc = i - rr * 34;
            int y = gy0 - 1 + rr;
            int x = gx0 - 1 + cc;
            float v = 0.f;
            if (y >= 0 && y < 256 && x >= 0 && x < 256) v = inp[(y << 8) + x];
            s_in[i] = v;
        }
        __syncthreads();

        float v[6][3];
#pragma unroll
        for (int rr = 0; rr < 6; rr++)
#pragma unroll
            for (int dx = 0; dx < 3; dx++)
                v[rr][dx] = s_in[(ly + rr) * 34 + tx + dx];

#pragma unroll
        for (int o = 0; o < 8; o++) {
            const float* wp = &s_w[(o * CIN + k) * 9];
            float w0 = wp[0], w1 = wp[1], w2 = wp[2];
            float w3 = wp[3], w4 = wp[4], w5 = wp[5];
            float w6 = wp[6], w7 = wp[7], w8 = wp[8];
#pragma unroll
            for (int r = 0; r < 4; r++) {
                float s = acc[o][r];
                s += v[r  ][0]*w0 + v[r  ][1]*w1 + v[r  ][2]*w2;
                s += v[r+1][0]*w3 + v[r+1][1]*w4 + v[r+1][2]*w5;
                s += v[r+2][0]*w6 + v[r+2][1]*w7 + v[r+2][2]*w8;
                acc[o][r] = s;
            }
        }
    }

    // bias + relu
#pragma unroll
    for (int o = 0; o < 8; o++) {
        float bb = bias[ocg*8 + o];
#pragma unroll
        for (int r = 0; r < 4; r++) acc[o][r] = fmaxf(acc[o][r] + bb, 0.f);
    }

    const int gy = gy0 + ly;

    if (FUSE) {   // += conv1x1(x2) + b1x1   (after relu, per reference)
#pragma unroll 4
        for (int k = 0; k < 64; k++) {
            const float* xp = x2 + (((size_t)b * 64 + k) << 16) + gx0 + tx;
            float xv[4];
#pragma unroll
            for (int r = 0; r < 4; r++) xv[r] = __ldg(xp + ((size_t)(gy + r) << 8));
#pragma unroll
            for (int o = 0; o < 8; o++) {
                float wk = s_w1[o*64 + k];
#pragma unroll
                for (int r = 0; r < 4; r++) acc[o][r] += wk * xv[r];
            }
        }
#pragma unroll
        for (int o = 0; o < 8; o++) {
            float bb = b1x1[ocg*8 + o];
#pragma unroll
            for (int r = 0; r < 4; r++) acc[o][r] += bb;
        }
    }

    // NCHW write
#pragma unroll
    for (int o = 0; o < 8; o++) {
        int oc = ocg*8 + o;
        float* op = out_nchw + (((size_t)b * 128 + oc) << 16) + gx0 + tx;
#pragma unroll
        for (int r = 0; r < 4; r++) op[(size_t)(gy + r) << 8] = acc[o][r];
    }
    // NHWC write (feature map for sampler)
    if (FUSE) {
#pragma unroll
        for (int r = 0; r < 4; r++) {
            float4 v0 = make_float4(acc[0][r], acc[1][r], acc[2][r], acc[3][r]);
            float4 v1 = make_float4(acc[4][r], acc[5][r], acc[6][r], acc[7][r]);
            float* tp = out_nhwc +
                ((((size_t)b << 16) + ((size_t)(gy + r) << 8) + gx0 + tx) << 7) + ocg * 8;
            ((float4*)tp)[0] = v0;
            ((float4*)tp)[1] = v1;
        }
    }
}

// ---------------------------------------------------------------------------
// Point kernel: 64 points per block, 256 threads.
//  gather (bilinear from NHWC feat) -> GEMM1 (128->256, relu)
//  -> GEMM2 (256->128) + c_last@w_fcc (64->128) + biases
//  -> write c, scatter-add into sums/cnt.
//  Thread mapping for gather/scatter: i = tid>>2 (point 0..63),
//  q = tid&3 (32-channel quarter).  Each point handled exactly once.
// ---------------------------------------------------------------------------
#define SA_STRIDE 132
#define SH_STRIDE 260
#define SCL_STRIDE 68
#define PK_SMEM_FLOATS (64*SA_STRIDE + 64*SH_STRIDE + 4096 + 64*SCL_STRIDE)

__global__ __launch_bounds__(256, 1)
void point_kernel(const float* __restrict__ p, const float* __restrict__ c_last,
                  const float* __restrict__ featT,
                  const float* __restrict__ w_fc1, const float* __restrict__ b_fc1,
                  const float* __restrict__ w_fc2, const float* __restrict__ b_fc2,
                  const float* __restrict__ w_fcc, const float* __restrict__ b_fcc,
                  float* __restrict__ c_out, float* __restrict__ sums,
                  float* __restrict__ cnt)
{
    extern __shared__ float sm[];
    float* s_a  = sm;                            // 64 x 132 (feat, later c)
    float* s_h1 = sm + 64*SA_STRIDE;             // 64 x 260 (hidden)
    float* s_w  = s_h1 + 64*SH_STRIDE;           // 4096 (weight chunk)
    float* s_cl = s_w + 4096;                    // 64 x 68 (c_last tile)

    const int tid = threadIdx.x;
    const int b   = blockIdx.y;
    const int n0  = blockIdx.x * 64;
    const int i   = tid >> 2;    // point index within block: 0..63
    const int q   = tid & 3;     // channel quarter: 32 floats each
    const int n   = n0 + i;
    const bool act = (n < NPTS);

    // ---- bilinear gather ----
    float xx = 0.f, yy = 0.f;
    if (act) {
        xx = p[((size_t)b * NPTS + n) * 3 + 0];
        yy = p[((size_t)b * NPTS + n) * 3 + 1];
    }
    {
        float px = fminf(fmaxf(xx * 255.f, 0.f), 255.f);
        float py = fminf(fmaxf(yy * 255.f, 0.f), 255.f);
        float x0f = floorf(px), y0f = floorf(py);
        int x0 = (int)x0f, y0 = (int)y0f;
        int x1 = min(x0 + 1, 255), y1 = min(y0 + 1, 255);
        float wx = px - x0f, wy = py - y0f;
        float w00 = (1.f-wx)*(1.f-wy), w01 = wx*(1.f-wy);
        float w10 = (1.f-wx)*wy,       w11 = wx*wy;
        const float* base = featT + ((size_t)b << 23);
        const float4* p00 = (const float4*)(base + ((size_t)((y0<<8)+x0) << 7) + q*32);
        const float4* p01 = (const float4*)(base + ((size_t)((y0<<8)+x1) << 7) + q*32);
        const float4* p10 = (const float4*)(base + ((size_t)((y1<<8)+x0) << 7) + q*32);
        const float4* p11 = (const float4*)(base + ((size_t)((y1<<8)+x1) << 7) + q*32);
        float4* dst = (float4*)(s_a + i*SA_STRIDE + q*32);
#pragma unroll
        for (int c4 = 0; c4 < 8; c4++) {
            float4 a = act ? p00[c4] : make_float4(0,0,0,0);
            float4 bq = act ? p01[c4] : make_float4(0,0,0,0);
            float4 cq = act ? p10[c4] : make_float4(0,0,0,0);
            float4 dq = act ? p11[c4] : make_float4(0,0,0,0);
            float4 r;
            r.x = a.x*w00 + bq.x*w01 + cq.x*w10 + dq.x*w11;
            r.y = a.y*w00 + bq.y*w01 + cq.y*w10 + dq.y*w11;
            r.z = a.z*w00 + bq.z*w01 + cq.z*w10 + dq.z*w11;
            r.w = a.w*w00 + bq.w*w01 + cq.w*w10 + dq.w*w11;
            dst[c4] = r;
        }
    }
    __syncthreads();

    const int cb = tid & 15;   // column lane  (cols cb + 16*j)
    const int pb = tid >> 4;   // point lane   (pts  pb + 16*r)

    // ---- GEMM1: H1[64][256] = relu(feat @ w_fc1 + b_fc1) ----
    float acc1[4][16];
#pragma unroll
    for (int r = 0; r < 4; r++)
#pragma unroll
        for (int j = 0; j < 16; j++) acc1[r][j] = 0.f;

    for (int kc = 0; kc < 128; kc += 16) {
        __syncthreads();
        for (int idx = tid; idx < 16*256; idx += 256) s_w[idx] = w_fc1[kc*256 + idx];
        __syncthreads();
#pragma unroll
        for (int kk = 0; kk < 16; kk++) {
            float a[4];
#pragma unroll
            for (int r = 0; r < 4; r++) a[r] = s_a[(pb + (r<<4)) * SA_STRIDE + kc + kk];
#pragma unroll
            for (int jh = 0; jh < 2; jh++) {
                float wv[8];
#pragma unroll
                for (int j = 0; j < 8; j++) wv[j] = s_w[kk*256 + cb + ((jh*8 + j) << 4)];
#pragma unroll
                for (int r = 0; r < 4; r++)
#pragma unroll
                    for (int j = 0; j < 8; j++) acc1[r][jh*8 + j] += a[r] * wv[j];
            }
        }
    }
    {
        float b1v[16];
#pragma unroll
        for (int j = 0; j < 16; j++) b1v[j] = b_fc1[cb + (j << 4)];
#pragma unroll
        for (int r = 0; r < 4; r++)
#pragma unroll
            for (int j = 0; j < 16; j++)
                s_h1[(pb + (r<<4)) * SH_STRIDE + cb + (j<<4)] = fmaxf(acc1[r][j] + b1v[j], 0.f);
    }

    // ---- GEMM2: C[64][128] = H1 @ w_fc2 ----
    float acc2[4][8];
#pragma unroll
    for (int r = 0; r < 4; r++)
#pragma unroll
        for (int j = 0; j < 8; j++) acc2[r][j] = 0.f;

    for (int kc = 0; kc < 256; kc += 32) {
        __syncthreads();
        for (int idx = tid; idx < 32*128; idx += 256) s_w[idx] = w_fc2[kc*128 + idx];
        __syncthreads();
#pragma unroll
        for (int kk = 0; kk < 32; kk++) {
            float a[4];
#pragma unroll
            for (int r = 0; r < 4; r++) a[r] = s_h1[(pb + (r<<4)) * SH_STRIDE + kc + kk];
            float wv[8];
#pragma unroll
            for (int j = 0; j < 8; j++) wv[j] = s_w[kk*128 + cb + (j<<4)];
#pragma unroll
            for (int r = 0; r < 4; r++)
#pragma unroll
                for (int j = 0; j < 8; j++) acc2[r][j] += a[r] * wv[j];
        }
    }

    // ---- + c_last @ w_fcc ----
    __syncthreads();
    for (int idx = tid; idx < 64*64; idx += 256) {
        int ii = idx >> 6, k = idx & 63;
        s_cl[ii*SCL_STRIDE + k] =
            (n0 + ii < NPTS) ? c_last[((size_t)b * NPTS + n0 + ii) * 64 + k] : 0.f;
    }
    for (int kc = 0; kc < 64; kc += 32) {
        __syncthreads();
        for (int idx = tid; idx < 32*128; idx += 256) s_w[idx] = w_fcc[kc*128 + idx];
        __syncthreads();
#pragma unroll
        for (int kk = 0; kk < 32; kk++) {
            float a[4];
#pragma unroll
            for (int r = 0; r < 4; r++) a[r] = s_cl[(pb + (r<<4)) * SCL_STRIDE + kc + kk];
            float wv[8];
#pragma unroll
            for (int j = 0; j < 8; j++) wv[j] = s_w[kk*128 + cb + (j<<4)];
#pragma unroll
            for (int r = 0; r < 4; r++)
#pragma unroll
                for (int j = 0; j < 8; j++) acc2[r][j] += a[r] * wv[j];
        }
    }

    // ---- biases, stage c tile in s_a ----
    {
        float b2v[8];
#pragma unroll
        for (int j = 0; j < 8; j++) b2v[j] = b_fc2[cb + (j<<4)] + b_fcc[cb + (j<<4)];
        __syncthreads();
#pragma unroll
        for (int r = 0; r < 4; r++)
#pragma unroll
            for (int j = 0; j < 8; j++)
                s_a[(pb + (r<<4)) * SA_STRIDE + cb + (j<<4)] = acc2[r][j] + b2v[j];
    }
    __syncthreads();

    // ---- write c (coalesced float4) ----
    {
        size_t cbase4 = ((size_t)b * NPTS + n0) * 32;   // float4 units
#pragma unroll
        for (int qq = 0; qq < 8; qq++) {
            int f4 = tid + qq*256;
            int ii = f4 >> 5;
            int c4 = f4 & 31;
            if (n0 + ii < NPTS) {
                float4 v = *(const float4*)(s_a + ii*SA_STRIDE + (c4 << 2));
                ((float4*)c_out)[cbase4 + (size_t)ii*32 + c4] = v;
            }
        }
    }

    // ---- scatter-add (each point exactly once, 4 threads x 32 ch) ----
    if (act) {
        int sx = min(max((int)(xx * 256.f), 0), 255);
        int sy = min(max((int)(yy * 256.f), 0), 255);
        int seg = sx + (sy << 8);
        float* sp = sums + ((((size_t)b << 16) + seg) << 7) + q * 32;
        const float* src = s_a + i*SA_STRIDE + q * 32;
#pragma unroll
        for (int c = 0; c < 32; c++) atomicAdd(sp + c, src[c]);
        if (q == 0) atomicAdd(cnt + ((size_t)b << 16) + seg, 1.f);
    }
}

// ---------------------------------------------------------------------------
// Normalize scatter sums -> before_pool (NCHW) + fused 2x2 maxpool -> out.
// ---------------------------------------------------------------------------
__global__ __launch_bounds__(256)
void finalize_kernel(const float* __restrict__ sums, const float* __restrict__ cnt,
                     float* __restrict__ before_pool, float* __restrict__ out)
{
    __shared__ float tile[64*129];
    __shared__ float s_inv[64];

    const int tid = threadIdx.x;
    const int b  = blockIdx.z;
    const int yp = blockIdx.y;
    const int xt = blockIdx.x;
    const int x0 = xt * 32, y0 = yp * 2;

    if (tid < 64) {
        int gseg = ((y0 + (tid >> 5)) << 8) + x0 + (tid & 31);
        float c = cnt[((size_t)b << 16) + gseg];
        s_inv[tid] = 1.f / fmaxf(c, 1.f);
    }
    __syncthreads();

#pragma unroll
    for (int qq = 0; qq < 8; qq++) {
        int f4 = tid + qq*256;
        int i  = f4 >> 5;
        int c4 = f4 & 31;
        int gseg = ((y0 + (i >> 5)) << 8) + x0 + (i & 31);
        float4 v = ((const float4*)sums)[((((size_t)b << 16) + gseg) << 5) + c4];
        float inv = s_inv[i];
        float* tp = tile + i*129 + (c4 << 2);
        tp[0] = v.x * inv; tp[1] = v.y * inv; tp[2] = v.z * inv; tp[3] = v.w * inv;
    }
    __syncthreads();

    const int xi = tid & 31, cg = tid >> 5;
#pragma unroll
    for (int cc = 0; cc < 16; cc++) {
        int ch = cg + (cc << 3);
        float r0 = tile[xi * 129 + ch];
        float r1 = tile[(32 + xi) * 129 + ch];
        size_t bp = ((size_t)(b*128 + ch)) << 16;
        before_pool[bp + ((size_t)y0 << 8) + x0 + xi]       = r0;
        before_pool[bp + ((size_t)(y0+1) << 8) + x0 + xi]   = r1;
        if (xi < 16) {
            float m0 = fmaxf(tile[(2*xi) * 129 + ch],      tile[(2*xi + 1) * 129 + ch]);
            float m1 = fmaxf(tile[(32 + 2*xi) * 129 + ch], tile[(33 + 2*xi) * 129 + ch]);
            out[(((size_t)(b*128 + ch)) << 14) + (yp << 7) + (x0 >> 1) + xi] = fmaxf(m0, m1);
        }
    }
}

// ---------------------------------------------------------------------------
// launch
// ---------------------------------------------------------------------------
extern "C" void kernel_launch(void* const* d_in, const int* in_sizes, int n_in,
                              void* d_out, int out_size)
{
    const float* p      = (const float*)d_in[0];
    const float* x_xy   = (const float*)d_in[1];
    const float* x2     = (const float*)d_in[2];
    const float* c_last = (const float*)d_in[3];
    const float* w1     = (const float*)d_in[4];
    const float* b1     = (const float*)d_in[5];
    const float* w2     = (const float*)d_in[6];
    const float* b2     = (const float*)d_in[7];
    const float* w1x1   = (const float*)d_in[8];
    const float* b1x1   = (const float*)d_in[9];
    const float* wfc1   = (const float*)d_in[10];
    const float* bfc1   = (const float*)d_in[11];
    const float* wfc2   = (const float*)d_in[12];
    const float* bfc2   = (const float*)d_in[13];
    const float* wfcc   = (const float*)d_in[14];
    const float* bfcc   = (const float*)d_in[15];

    float* out        = (float*)d_out;
    float* out_pool   = out + OFF_POOL;
    float* out_bp     = out + OFF_BP;
    float* out_xafter = out + OFF_XAFTER;
    float* out_c      = out + OFF_C;

    float *h1, *featT, *sums, *cntp;
    cudaGetSymbolAddress((void**)&h1,    g_h1);
    cudaGetSymbolAddress((void**)&featT, g_featT);
    cudaGetSymbolAddress((void**)&sums,  g_sums);
    cudaGetSymbolAddress((void**)&cntp,  g_cnt);

    // zero scatter scratch (re-done every launch / graph replay)
    zero_kernel<<<(4194304 + 255) / 256, 256>>>(sums, 4194304);
    zero_kernel<<<(32768 + 255) / 256, 256>>>(cntp, 32768);

    // conv1: x_xy -> h1 (relu)
    conv3x3_kernel<64, false><<<dim3(8, 8, 32), 256>>>(
        x_xy, w1, b1, nullptr, nullptr, nullptr, h1, nullptr);

    // conv2 + fused 1x1: h1 -> x_after (NCHW in d_out) + featT (NHWC scratch)
    conv3x3_kernel<128, true><<<dim3(8, 8, 32), 256>>>(
        h1, w2, b2, x2, w1x1, b1x1, out_xafter, featT);

    // point pipeline
    const int pk_smem = PK_SMEM_FLOATS * 4;
    cudaFuncSetAttribute(point_kernel, cudaFuncAttributeMaxDynamicSharedMemorySize,
                         pk_smem);
    point_kernel<<<dim3((NPTS + 63) / 64, 2), 256, pk_smem>>>(
        p, c_last, featT, wfc1, bfc1, wfc2, bfc2, wfcc, bfcc,
        out_c, sums, cntp);

    // normalize + maxpool
    finalize_kernel<<<dim3(8, 128, 2), 256>>>(sums, cntp, out_bp, out_pool);
}